// round 11
// baseline (speedup 1.0000x reference)
#include <cuda_runtime.h>
#include <cuda_bf16.h>
#include <cstdint>
#include <math.h>

#define NI 128
#define RR 36
#define WW 50
#define DD 1024
#define MM (NI*RR)      // 4608
#define NN (NI*WW)      // 6400
#define K3 3072
#define BK 64
#define KSTEPS (K3/BK)  // 48
#define GCH 8           // gram K chunks

// ---------------- device scratch (allocation-free rule) ----------------
// Referenced ONLY from device code (host-side symbol pass was the R4/R9 bug).
__device__ float         g_attn[(size_t)MM * NN];   // 118 MB fp32
__device__ __nv_bfloat16 g_abf[(size_t)MM * K3];    // 28 MB  [hi|hi|lo]
__device__ __nv_bfloat16 g_bbf[(size_t)NN * K3];    // 39 MB  [hi|lo|hi]
__device__ float         g_gram_part[NI * GCH * RR * RR]; // 5.3 MB
__device__ float         g_gram[NI * RR * RR];
__device__ float         g_w1[NI * WW];
__device__ float         g_scores[NI * NI];

// ---------------- baseline-ISA PTX helpers ----------------
__device__ __forceinline__ uint32_t smem_u32(const void* p) {
    uint32_t a;
    asm("{ .reg .u64 t; cvta.to.shared.u64 t, %1; cvt.u32.u64 %0, t; }" : "=r"(a) : "l"(p));
    return a;
}
#define CP_ASYNC_16(dst_u32, src_ptr) \
    asm volatile("cp.async.cg.shared.global [%0], [%1], 16;" :: "r"(dst_u32), "l"(src_ptr))
#define CP_COMMIT()  asm volatile("cp.async.commit_group;" ::: "memory")
#define CP_WAIT(n)   asm volatile("cp.async.wait_group %0;" :: "n"(n) : "memory")

#define MMA_BF16(c, a0, a1, a2, a3, b0, b1) \
    asm volatile("mma.sync.aligned.m16n8k16.row.col.f32.bf16.bf16.f32 " \
        "{%0,%1,%2,%3}, {%4,%5,%6,%7}, {%8,%9}, {%0,%1,%2,%3};" \
        : "+f"((c)[0]), "+f"((c)[1]), "+f"((c)[2]), "+f"((c)[3]) \
        : "r"(a0), "r"(a1), "r"(a2), "r"(a3), "r"(b0), "r"(b1))

// ---------------------------------------------------------------------------
// Convert: fp32 -> bf16 hi/lo split, K'=3072 layout. Destination selected
// inside the kernel. MODE 1 additionally computes g_w1 (block == one row).
//   mode 0 (A -> g_abf): [hi | hi | lo]
//   mode 1 (B -> g_bbf): [hi | lo | hi]
// ---------------------------------------------------------------------------
template <int MODE>
__global__ __launch_bounds__(256) void convert_split(const float* __restrict__ src) {
    __nv_bfloat16* __restrict__ dst = (MODE == 0) ? g_abf : g_bbf;
    const size_t idx4 = ((size_t)blockIdx.x * 256 + threadIdx.x) * 4;
    const int m = (int)(idx4 / DD);
    const int k = (int)(idx4 % DD);
    float4 v = *(const float4*)(src + idx4);
    union { __nv_bfloat162 b2[2]; uint2 u; } hv, lv;
    __nv_bfloat16 h0 = __float2bfloat16(v.x);
    __nv_bfloat16 h1 = __float2bfloat16(v.y);
    __nv_bfloat16 h2 = __float2bfloat16(v.z);
    __nv_bfloat16 h3 = __float2bfloat16(v.w);
    hv.b2[0] = __nv_bfloat162(h0, h1);
    hv.b2[1] = __nv_bfloat162(h2, h3);
    lv.b2[0] = __nv_bfloat162(__float2bfloat16(v.x - __bfloat162float(h0)),
                              __float2bfloat16(v.y - __bfloat162float(h1)));
    lv.b2[1] = __nv_bfloat162(__float2bfloat16(v.z - __bfloat162float(h2)),
                              __float2bfloat16(v.w - __bfloat162float(h3)));
    __nv_bfloat16* base = dst + (size_t)m * K3 + k;
    *(uint2*)(base)        = hv.u;
    *(uint2*)(base + 1024) = (MODE == 0) ? hv.u : lv.u;
    *(uint2*)(base + 2048) = (MODE == 0) ? lv.u : hv.u;

    if (MODE == 1) {
        // block covers exactly one (c,w) row of 1024 floats -> |s| reduce
        __shared__ float wsum[8];
        float sq = v.x * v.x + v.y * v.y + v.z * v.z + v.w * v.w;
        #pragma unroll
        for (int off = 16; off; off >>= 1) sq += __shfl_xor_sync(0xFFFFFFFFu, sq, off);
        const int wid = threadIdx.x >> 5;
        if ((threadIdx.x & 31) == 0) wsum[wid] = sq;
        __syncthreads();
        if (threadIdx.x == 0) {
            float s = 0.f;
            #pragma unroll
            for (int q = 0; q < 8; q++) s += wsum[q];
            g_w1[blockIdx.x] = sqrtf(s);
        }
    }
}

// ---------------------------------------------------------------------------
// mma.sync bf16 NT GEMM: g_attn[4608 x 6400] = A'[4608 x 3072] * B'[6400 x 3072]^T
// 128x128 tile, 256 thr (8 warps = 4m x 2n, 32x64 each), BK=64, 3-stage cp.async.
// Fragments fed by explicit per-thread 4-byte smem loads.
// ---------------------------------------------------------------------------
#define ROWB 144                      // padded row stride in bytes (64 bf16 = 128B + 16 pad)
#define STAGE_BYTES (2 * 128 * ROWB)  // 36864
#define GEMM_SMEM (3 * STAGE_BYTES)   // 110592

__device__ __forceinline__ void load_stage(uint32_t sbase, int slot,
                                           const __nv_bfloat16* __restrict__ Arow,
                                           const __nv_bfloat16* __restrict__ Brow,
                                           int k0, int tid) {
    const uint32_t st = sbase + slot * STAGE_BYTES;
    // A: 128 rows x 8 segs of 16B; B same, at +128*ROWB
    #pragma unroll
    for (int h = 0; h < 4; h++) {
        const int c = tid + h * 256;     // 0..1023
        const int row = c >> 3;          // 0..127
        const int seg = c & 7;           // 0..7
        CP_ASYNC_16(st + row * ROWB + seg * 16,
                    Arow + (size_t)row * K3 + k0 + seg * 8);
        CP_ASYNC_16(st + 128 * ROWB + row * ROWB + seg * 16,
                    Brow + (size_t)row * K3 + k0 + seg * 8);
    }
}

__global__ __launch_bounds__(256) void gemm_mma_bf16() {
    extern __shared__ char smem[];
    const uint32_t sbase = smem_u32(smem);
    const int tid = threadIdx.x;
    const int wid = tid >> 5;
    const int lane = tid & 31;
    const int warp_m = wid & 3;          // rows 32*warp_m
    const int warp_n = wid >> 2;         // cols 64*warp_n
    const int bm = blockIdx.y * 128;
    const int bn = blockIdx.x * 128;
    const int tg = lane >> 2;            // 0..7
    const int t4 = lane & 3;             // 0..3

    const __nv_bfloat16* Arow = g_abf + (size_t)bm * K3;
    const __nv_bfloat16* Brow = g_bbf + (size_t)bn * K3;

    float acc[2][8][4];
    #pragma unroll
    for (int i = 0; i < 2; i++)
        #pragma unroll
        for (int j = 0; j < 8; j++)
            #pragma unroll
            for (int q = 0; q < 4; q++) acc[i][j][q] = 0.f;

    // A frag: a0 = {A[m][k],A[m][k+1]}, m = warp_m*32 + tg (+8/+16), k = 2*t4 (+8)
    const uint32_t aoff = (uint32_t)((warp_m * 32 + tg) * ROWB + t4 * 4);
    // B frag ([n][k] storage): n = warp_n*64 + tg, k = 2*t4 (+8)
    const uint32_t boff = (uint32_t)(128 * ROWB + (warp_n * 64 + tg) * ROWB + t4 * 4);

    load_stage(sbase, 0, Arow, Brow, 0, tid);  CP_COMMIT();
    load_stage(sbase, 1, Arow, Brow, BK, tid); CP_COMMIT();

    int slot = 0;
    for (int t = 0; t < KSTEPS; t++) {
        CP_WAIT(1);
        __syncthreads();
        if (t + 2 < KSTEPS)
            load_stage(sbase, (slot + 2) % 3, Arow, Brow, (t + 2) * BK, tid);
        CP_COMMIT();

        const char* st = smem + slot * STAGE_BYTES;
        #pragma unroll
        for (int kk = 0; kk < 4; kk++) {       // four k16 halves of BK=64
            uint32_t a[2][4];
            uint32_t b[4][4];
            #pragma unroll
            for (int mi = 0; mi < 2; mi++) {
                const char* pa = st + aoff + mi * 16 * ROWB + kk * 32;
                a[mi][0] = *(const uint32_t*)(pa);
                a[mi][1] = *(const uint32_t*)(pa + 8 * ROWB);
                a[mi][2] = *(const uint32_t*)(pa + 16);
                a[mi][3] = *(const uint32_t*)(pa + 8 * ROWB + 16);
            }
            #pragma unroll
            for (int j = 0; j < 4; j++) {
                const char* pb = st + boff + j * 16 * ROWB + kk * 32;
                b[j][0] = *(const uint32_t*)(pb);                 // n-tile 2j,   k 0-7
                b[j][1] = *(const uint32_t*)(pb + 16);            // n-tile 2j,   k 8-15
                b[j][2] = *(const uint32_t*)(pb + 8 * ROWB);      // n-tile 2j+1, k 0-7
                b[j][3] = *(const uint32_t*)(pb + 8 * ROWB + 16); // n-tile 2j+1, k 8-15
            }
            #pragma unroll
            for (int mi = 0; mi < 2; mi++)
                #pragma unroll
                for (int j = 0; j < 4; j++) {
                    MMA_BF16(acc[mi][2 * j],     a[mi][0], a[mi][1], a[mi][2], a[mi][3],
                             b[j][0], b[j][1]);
                    MMA_BF16(acc[mi][2 * j + 1], a[mi][0], a[mi][1], a[mi][2], a[mi][3],
                             b[j][2], b[j][3]);
                }
        }
        slot = (slot + 1) % 3;
        __syncthreads();
    }

    // epilogue: C frag m16n8: thread holds (row tg + {0,8}, col t4*2 + {0,1})
    const int r0 = bm + warp_m * 32 + tg;
    const int c0 = bn + warp_n * 64 + t4 * 2;
    #pragma unroll
    for (int mi = 0; mi < 2; mi++) {
        #pragma unroll
        for (int j = 0; j < 8; j++) {
            float* p0 = g_attn + (size_t)(r0 + mi * 16) * NN + c0 + j * 8;
            float* p1 = g_attn + (size_t)(r0 + mi * 16 + 8) * NN + c0 + j * 8;
            *(float2*)p0 = make_float2(acc[mi][j][0], acc[mi][j][1]);
            *(float2*)p1 = make_float2(acc[mi][j][2], acc[mi][j][3]);
        }
    }
}

// ---------------------------------------------------------------------------
// Gram, parallel: partial G over 128-d chunk per block (8 x 128 grid), then reduce
// ---------------------------------------------------------------------------
__global__ __launch_bounds__(256) void gram_partial(const float* __restrict__ im) {
    __shared__ float sIm[RR][130];
    const int ch = blockIdx.x;           // 0..7
    const int i  = blockIdx.y;           // 0..127
    const int tid = threadIdx.x;
    const int PAIRS = RR * RR;           // 1296
    const int d0 = ch * 128;

    for (int idx = tid; idx < RR * 128; idx += 256) {
        int r = idx >> 7, k = idx & 127;
        sIm[r][k] = im[(size_t)(i * RR + r) * DD + d0 + k];
    }
    __syncthreads();

    float* outp = g_gram_part + (size_t)(i * GCH + ch) * PAIRS;
    #pragma unroll
    for (int p = 0; p < 6; p++) {
        const int pair = tid + p * 256;
        if (pair < PAIRS) {
            const int r1 = pair / RR, r2 = pair % RR;
            float sum = 0.f;
            #pragma unroll 8
            for (int k = 0; k < 128; k++) sum += sIm[r1][k] * sIm[r2][k];
            outp[pair] = sum;
        }
    }
}

__global__ __launch_bounds__(256) void gram_reduce() {
    const int idx = blockIdx.x * 256 + threadIdx.x;   // over NI*1296
    if (idx < NI * RR * RR) {
        const int i = idx / (RR * RR);
        const int p = idx % (RR * RR);
        const float* base = g_gram_part + (size_t)i * GCH * RR * RR + p;
        float s = 0.f;
        #pragma unroll
        for (int c = 0; c < GCH; c++) s += base[(size_t)c * RR * RR];
        g_gram[idx] = s;
    }
}

// ---------------------------------------------------------------------------
// Per (c,i) pair: leaky/mask/l2norm, softmax over r, w12 + w2 via Gram
// quadratic form (parallel U = t*G), LSE over valid words.
// ---------------------------------------------------------------------------
__global__ __launch_bounds__(128) void pair_kernel(const int* __restrict__ s_l) {
    __shared__ __align__(16) float rawS[RR][WW];
    __shared__ __align__(16) float aS[RR][WW];
    __shared__ __align__(16) float tS[WW][RR];
    __shared__ __align__(16) float gS[RR][RR];
    __shared__ __align__(16) float U[WW][RR];
    __shared__ float red[WW];
    __shared__ float w12s[WW];

    const int c = blockIdx.x, i = blockIdx.y;
    const int tid = threadIdx.x;
    const int len = s_l[c];

    for (int idx = tid; idx < RR * WW; idx += 128) {
        int r = idx / WW, w = idx % WW;
        rawS[r][w] = g_attn[(size_t)(i * RR + r) * NN + c * WW + w];
    }
    for (int idx = tid; idx < RR * RR; idx += 128)
        gS[idx / RR][idx % RR] = g_gram[i * RR * RR + idx];
    __syncthreads();

    // per-region: leaky_relu(0.1), word mask, L2-normalize over w
    if (tid < RR) {
        const int r = tid;
        float ss = 0.f;
        #pragma unroll 10
        for (int w = 0; w < WW; w++) {
            float v = rawS[r][w];
            v = (v > 0.f) ? v : 0.1f * v;
            v = (w < len) ? v : 0.f;
            ss += v * v;
            aS[r][w] = v;
        }
        float inv = 1.f / (sqrtf(ss) + 1e-8f);
        #pragma unroll 10
        for (int w = 0; w < WW; w++) aS[r][w] *= inv;
    }
    __syncthreads();

    // per-word: softmax over regions (lambda=9), and w12 = sum t * raw
    if (tid < WW) {
        const int w = tid;
        float mx = -1e30f;
        #pragma unroll
        for (int r = 0; r < RR; r++) mx = fmaxf(mx, aS[r][w]);
        float ssum = 0.f;
        #pragma unroll
        for (int r = 0; r < RR; r++) {
            float e = __expf(9.f * (aS[r][w] - mx));
            tS[w][r] = e;
            ssum += e;
        }
        const float inv = 1.f / ssum;
        float w12 = 0.f;
        #pragma unroll
        for (int r = 0; r < RR; r++) {
            float tv = tS[w][r] * inv;
            tS[w][r] = tv;
            w12 += tv * rawS[r][w];
        }
        w12s[w] = w12;
    }
    __syncthreads();

    // U[w][r0..r0+3] = sum_r2 t[w][r2] * G[r2][r0..r0+3]   (450 float4 items)
    for (int idx = tid; idx < WW * (RR / 4); idx += 128) {
        const int w = idx / (RR / 4);
        const int j = idx % (RR / 4);
        float4 acc = make_float4(0.f, 0.f, 0.f, 0.f);
        #pragma unroll
        for (int r2 = 0; r2 < RR; r2++) {
            const float tv = tS[w][r2];
            const float4 g4 = *(const float4*)&gS[r2][4 * j];
            acc.x += tv * g4.x; acc.y += tv * g4.y;
            acc.z += tv * g4.z; acc.w += tv * g4.w;
        }
        *(float4*)&U[w][4 * j] = acc;
    }
    __syncthreads();

    // per-word: w2^2 = t . U, similarity, masked exp
    if (tid < WW) {
        const int w = tid;
        float w2sq = 0.f;
        #pragma unroll
        for (int r = 0; r < RR; r++) w2sq += U[w][r] * tS[w][r];
        const float w2 = sqrtf(w2sq);
        const float w1v = g_w1[c * WW + w];
        const float denom = fmaxf(w1v * w2, 1e-8f);
        const float sim = w12s[w] / denom;
        red[w] = (w < len) ? expf(6.f * sim) : 0.f;
    }
    __syncthreads();

    if (tid == 0) {
        float sum = 0.f;
        #pragma unroll 10
        for (int w = 0; w < WW; w++) sum += red[w];
        g_scores[i * NI + c] = logf(sum) / 6.f;
    }
}

// ---------------------------------------------------------------------------
// Hinge loss with hardest negatives
// ---------------------------------------------------------------------------
__global__ __launch_bounds__(128) void loss_kernel(float* __restrict__ out) {
    __shared__ float diag[NI];
    __shared__ float partial[NI];
    const int t = threadIdx.x;
    diag[t] = g_scores[t * NI + t];
    __syncthreads();
    const float dt = diag[t];
    float m1 = 0.f, m2 = 0.f;
    for (int c = 0; c < NI; c++) {
        if (c != t) {
            float v = 0.2f + g_scores[t * NI + c] - dt;
            m1 = fmaxf(m1, fmaxf(v, 0.f));
            float u = 0.2f + g_scores[c * NI + t] - dt;
            m2 = fmaxf(m2, fmaxf(u, 0.f));
        }
    }
    partial[t] = m1 + m2;
    __syncthreads();
    if (t == 0) {
        float s = 0.f;
        for (int k = 0; k < NI; k++) s += partial[k];
        out[0] = s;
    }
}

// ---------------------------------------------------------------------------
extern "C" void kernel_launch(void* const* d_in, const int* in_sizes, int n_in,
                              void* d_out, int out_size) {
    const float* im  = (const float*)d_in[0];   // (128, 36, 1024) f32
    const float* s   = (const float*)d_in[1];   // (128, 50, 1024) f32
    const int*   s_l = (const int*)d_in[2];     // (128,) i32
    float* out = (float*)d_out;

    cudaFuncSetAttribute(gemm_mma_bf16, cudaFuncAttributeMaxDynamicSharedMemorySize,
                         GEMM_SMEM);

    convert_split<0><<<MM * DD / (256 * 4), 256>>>(im);
    convert_split<1><<<NN * DD / (256 * 4), 256>>>(s);     // also computes g_w1
    gemm_mma_bf16<<<dim3(NN / 128, MM / 128), 256, GEMM_SMEM>>>();
    gram_partial<<<dim3(GCH, NI), 256>>>(im);
    gram_reduce<<<(NI * RR * RR + 255) / 256, 256>>>();
    pair_kernel<<<dim3(NI, NI), 128>>>(s_l);
    loss_kernel<<<1, 128>>>(out);
}

// round 14
// speedup vs baseline: 1.4231x; 1.4231x over previous
#include <cuda_runtime.h>
#include <cuda_bf16.h>
#include <cstdint>
#include <math.h>

#define NI 128
#define RR 36
#define WW 50
#define DD 1024
#define MM (NI*RR)      // 4608
#define NN (NI*WW)      // 6400
#define K3 3072
#define BK 32
#define KSTEPS (K3/BK)  // 96
#define GCH 8           // gram K chunks

// ---------------- device scratch (allocation-free rule) ----------------
// Referenced ONLY from device code (host-side symbol pass was the R4/R9 bug).
__device__ float         g_attn[(size_t)MM * NN];   // 118 MB fp32
__device__ __nv_bfloat16 g_abf[(size_t)MM * K3];    // 28 MB  [hi|hi|lo]
__device__ __nv_bfloat16 g_bbf[(size_t)NN * K3];    // 39 MB  [hi|lo|hi]
__device__ float         g_gram_part[NI * GCH * RR * RR]; // 5.3 MB
__device__ float         g_gram[NI * RR * RR];
__device__ float         g_w1[NI * WW];
__device__ float         g_scores[NI * NI];

// ---------------- baseline-ISA PTX helpers ----------------
__device__ __forceinline__ uint32_t smem_u32(const void* p) {
    uint32_t a;
    asm("{ .reg .u64 t; cvta.to.shared.u64 t, %1; cvt.u32.u64 %0, t; }" : "=r"(a) : "l"(p));
    return a;
}
#define CP_ASYNC_16(dst_u32, src_ptr) \
    asm volatile("cp.async.cg.shared.global [%0], [%1], 16;" :: "r"(dst_u32), "l"(src_ptr))
#define CP_COMMIT()  asm volatile("cp.async.commit_group;" ::: "memory")
#define CP_WAIT(n)   asm volatile("cp.async.wait_group %0;" :: "n"(n) : "memory")

#define MMA_BF16(c, a0, a1, a2, a3, b0, b1) \
    asm volatile("mma.sync.aligned.m16n8k16.row.col.f32.bf16.bf16.f32 " \
        "{%0,%1,%2,%3}, {%4,%5,%6,%7}, {%8,%9}, {%0,%1,%2,%3};" \
        : "+f"((c)[0]), "+f"((c)[1]), "+f"((c)[2]), "+f"((c)[3]) \
        : "r"(a0), "r"(a1), "r"(a2), "r"(a3), "r"(b0), "r"(b1))

// ---------------------------------------------------------------------------
// Convert: fp32 -> bf16 hi/lo split, K'=3072 layout. Destination selected
// inside the kernel. MODE 1 additionally computes g_w1 (block == one row).
//   mode 0 (A -> g_abf): [hi | hi | lo]
//   mode 1 (B -> g_bbf): [hi | lo | hi]
// ---------------------------------------------------------------------------
template <int MODE>
__global__ __launch_bounds__(256) void convert_split(const float* __restrict__ src) {
    __nv_bfloat16* __restrict__ dst = (MODE == 0) ? g_abf : g_bbf;
    const size_t idx4 = ((size_t)blockIdx.x * 256 + threadIdx.x) * 4;
    const int m = (int)(idx4 / DD);
    const int k = (int)(idx4 % DD);
    float4 v = *(const float4*)(src + idx4);
    union { __nv_bfloat162 b2[2]; uint2 u; } hv, lv;
    __nv_bfloat16 h0 = __float2bfloat16(v.x);
    __nv_bfloat16 h1 = __float2bfloat16(v.y);
    __nv_bfloat16 h2 = __float2bfloat16(v.z);
    __nv_bfloat16 h3 = __float2bfloat16(v.w);
    hv.b2[0] = __nv_bfloat162(h0, h1);
    hv.b2[1] = __nv_bfloat162(h2, h3);
    lv.b2[0] = __nv_bfloat162(__float2bfloat16(v.x - __bfloat162float(h0)),
                              __float2bfloat16(v.y - __bfloat162float(h1)));
    lv.b2[1] = __nv_bfloat162(__float2bfloat16(v.z - __bfloat162float(h2)),
                              __float2bfloat16(v.w - __bfloat162float(h3)));
    __nv_bfloat16* base = dst + (size_t)m * K3 + k;
    *(uint2*)(base)        = hv.u;
    *(uint2*)(base + 1024) = (MODE == 0) ? hv.u : lv.u;
    *(uint2*)(base + 2048) = (MODE == 0) ? lv.u : hv.u;

    if (MODE == 1) {
        // block covers exactly one (c,w) row of 1024 floats -> |s| reduce
        __shared__ float wsum[8];
        float sq = v.x * v.x + v.y * v.y + v.z * v.z + v.w * v.w;
        #pragma unroll
        for (int off = 16; off; off >>= 1) sq += __shfl_xor_sync(0xFFFFFFFFu, sq, off);
        const int wid = threadIdx.x >> 5;
        if ((threadIdx.x & 31) == 0) wsum[wid] = sq;
        __syncthreads();
        if (threadIdx.x == 0) {
            float s = 0.f;
            #pragma unroll
            for (int q = 0; q < 8; q++) s += wsum[q];
            g_w1[blockIdx.x] = sqrtf(s);
        }
    }
}

// ---------------------------------------------------------------------------
// mma.sync bf16 NT GEMM (R10 config): 128x128 tile, 256 thr (4m x 2n warps),
// BK=32, 3-stage cp.async, ROWB=80 padded rows, explicit smem fragment loads.
// ---------------------------------------------------------------------------
#define ROWB 80                       // padded row stride in bytes (40 bf16)
#define STAGE_BYTES (2 * 128 * ROWB)  // 20480
#define GEMM_SMEM (3 * STAGE_BYTES)   // 61440

__device__ __forceinline__ void load_stage(uint32_t sbase, int slot,
                                           const __nv_bfloat16* __restrict__ Arow,
                                           const __nv_bfloat16* __restrict__ Brow,
                                           int k0, int tid) {
    const uint32_t st = sbase + slot * STAGE_BYTES;
    #pragma unroll
    for (int h = 0; h < 2; h++) {
        const int c = tid + h * 256;
        const int row = c >> 2;          // 0..127
        const int seg = c & 3;           // 0..3 (16B each)
        CP_ASYNC_16(st + row * ROWB + seg * 16,
                    Arow + (size_t)row * K3 + k0 + seg * 8);
        CP_ASYNC_16(st + 128 * ROWB + row * ROWB + seg * 16,
                    Brow + (size_t)row * K3 + k0 + seg * 8);
    }
}

__global__ __launch_bounds__(256) void gemm_mma_bf16() {
    extern __shared__ char smem[];
    const uint32_t sbase = smem_u32(smem);
    const int tid = threadIdx.x;
    const int wid = tid >> 5;
    const int lane = tid & 31;
    const int warp_m = wid & 3;          // rows 32*warp_m
    const int warp_n = wid >> 2;         // cols 64*warp_n
    const int bm = blockIdx.y * 128;
    const int bn = blockIdx.x * 128;
    const int tg = lane >> 2;            // 0..7
    const int t4 = lane & 3;             // 0..3

    const __nv_bfloat16* Arow = g_abf + (size_t)bm * K3;
    const __nv_bfloat16* Brow = g_bbf + (size_t)bn * K3;

    float acc[2][8][4];
    #pragma unroll
    for (int i = 0; i < 2; i++)
        #pragma unroll
        for (int j = 0; j < 8; j++)
            #pragma unroll
            for (int q = 0; q < 4; q++) acc[i][j][q] = 0.f;

    // A frag: a0 = {A[m][k],A[m][k+1]}, m = warp_m*32 + tg (+8/+16), k = 2*t4 (+8)
    const uint32_t aoff = (uint32_t)((warp_m * 32 + tg) * ROWB + t4 * 4);
    // B frag ([n][k] storage): n = warp_n*64 + tg, k = 2*t4 (+8)
    const uint32_t boff = (uint32_t)(128 * ROWB + (warp_n * 64 + tg) * ROWB + t4 * 4);

    load_stage(sbase, 0, Arow, Brow, 0, tid);  CP_COMMIT();
    load_stage(sbase, 1, Arow, Brow, BK, tid); CP_COMMIT();

    int slot = 0;
    for (int t = 0; t < KSTEPS; t++) {
        CP_WAIT(1);
        __syncthreads();
        if (t + 2 < KSTEPS)
            load_stage(sbase, (slot + 2) % 3, Arow, Brow, (t + 2) * BK, tid);
        CP_COMMIT();

        const char* st = smem + slot * STAGE_BYTES;
        #pragma unroll
        for (int kk = 0; kk < 2; kk++) {       // two k16 halves of BK=32
            uint32_t a[2][4];
            uint32_t b[4][4];
            #pragma unroll
            for (int mi = 0; mi < 2; mi++) {
                const char* pa = st + aoff + mi * 16 * ROWB + kk * 32;
                a[mi][0] = *(const uint32_t*)(pa);
                a[mi][1] = *(const uint32_t*)(pa + 8 * ROWB);
                a[mi][2] = *(const uint32_t*)(pa + 16);
                a[mi][3] = *(const uint32_t*)(pa + 8 * ROWB + 16);
            }
            #pragma unroll
            for (int j = 0; j < 4; j++) {
                const char* pb = st + boff + j * 16 * ROWB + kk * 32;
                b[j][0] = *(const uint32_t*)(pb);                 // n-tile 2j,   k 0-7
                b[j][1] = *(const uint32_t*)(pb + 16);            // n-tile 2j,   k 8-15
                b[j][2] = *(const uint32_t*)(pb + 8 * ROWB);      // n-tile 2j+1, k 0-7
                b[j][3] = *(const uint32_t*)(pb + 8 * ROWB + 16); // n-tile 2j+1, k 8-15
            }
            #pragma unroll
            for (int mi = 0; mi < 2; mi++)
                #pragma unroll
                for (int j = 0; j < 4; j++) {
                    MMA_BF16(acc[mi][2 * j],     a[mi][0], a[mi][1], a[mi][2], a[mi][3],
                             b[j][0], b[j][1]);
                    MMA_BF16(acc[mi][2 * j + 1], a[mi][0], a[mi][1], a[mi][2], a[mi][3],
                             b[j][2], b[j][3]);
                }
        }
        slot = (slot + 1) % 3;
        __syncthreads();
    }

    // epilogue: C frag m16n8: thread holds (row tg + {0,8}, col t4*2 + {0,1})
    const int r0 = bm + warp_m * 32 + tg;
    const int c0 = bn + warp_n * 64 + t4 * 2;
    #pragma unroll
    for (int mi = 0; mi < 2; mi++) {
        #pragma unroll
        for (int j = 0; j < 8; j++) {
            float* p0 = g_attn + (size_t)(r0 + mi * 16) * NN + c0 + j * 8;
            float* p1 = g_attn + (size_t)(r0 + mi * 16 + 8) * NN + c0 + j * 8;
            *(float2*)p0 = make_float2(acc[mi][j][0], acc[mi][j][1]);
            *(float2*)p1 = make_float2(acc[mi][j][2], acc[mi][j][3]);
        }
    }
}

// ---------------------------------------------------------------------------
// Gram, parallel + 2x2 register tiling: partial G over 128-d chunk per block
// (grid 8 x 128). 18x18 = 324 2x2-tiles; 1 word/FMA via float4 LDS.
// ---------------------------------------------------------------------------
__global__ __launch_bounds__(256) void gram_partial(const float* __restrict__ im) {
    __shared__ __align__(16) float sIm[RR][132];
    const int ch = blockIdx.x;           // 0..7
    const int i  = blockIdx.y;           // 0..127
    const int tid = threadIdx.x;
    const int PAIRS = RR * RR;           // 1296
    const int d0 = ch * 128;

    for (int idx = tid; idx < RR * 32; idx += 256) {
        int r = idx >> 5, k4 = idx & 31;
        *(float4*)&sIm[r][k4 * 4] =
            *(const float4*)(im + (size_t)(i * RR + r) * DD + d0 + k4 * 4);
    }
    __syncthreads();

    float* outp = g_gram_part + (size_t)(i * GCH + ch) * PAIRS;
    #pragma unroll
    for (int p = 0; p < 2; p++) {
        const int tile = tid + p * 256;         // 0..323
        if (tile < 324) {
            const int r1 = 2 * (tile / 18);
            const int r2 = 2 * (tile % 18);
            float s00 = 0.f, s01 = 0.f, s10 = 0.f, s11 = 0.f;
            #pragma unroll 8
            for (int k4 = 0; k4 < 32; k4++) {
                const float4 a0 = *(const float4*)&sIm[r1][k4 * 4];
                const float4 a1 = *(const float4*)&sIm[r1 + 1][k4 * 4];
                const float4 b0 = *(const float4*)&sIm[r2][k4 * 4];
                const float4 b1 = *(const float4*)&sIm[r2 + 1][k4 * 4];
                s00 += a0.x * b0.x + a0.y * b0.y + a0.z * b0.z + a0.w * b0.w;
                s01 += a0.x * b1.x + a0.y * b1.y + a0.z * b1.z + a0.w * b1.w;
                s10 += a1.x * b0.x + a1.y * b0.y + a1.z * b0.z + a1.w * b0.w;
                s11 += a1.x * b1.x + a1.y * b1.y + a1.z * b1.z + a1.w * b1.w;
            }
            outp[r1 * RR + r2]           = s00;
            outp[r1 * RR + r2 + 1]       = s01;
            outp[(r1 + 1) * RR + r2]     = s10;
            outp[(r1 + 1) * RR + r2 + 1] = s11;
        }
    }
}

__global__ __launch_bounds__(256) void gram_reduce() {
    const int idx = blockIdx.x * 256 + threadIdx.x;   // over NI*1296
    if (idx < NI * RR * RR) {
        const int i = idx / (RR * RR);
        const int p = idx % (RR * RR);
        const float* base = g_gram_part + (size_t)i * GCH * RR * RR + p;
        float s = 0.f;
        #pragma unroll
        for (int c = 0; c < GCH; c++) s += base[(size_t)c * RR * RR];
        g_gram[idx] = s;
    }
}

// ---------------------------------------------------------------------------
// Per (c,i) pair: leaky/mask/l2norm, softmax over r, w12 + w2 via Gram
// quadratic form (parallel U = t*G), LSE over valid words.
// ---------------------------------------------------------------------------
__global__ __launch_bounds__(128) void pair_kernel(const int* __restrict__ s_l) {
    __shared__ __align__(16) float rawS[RR][WW];
    __shared__ __align__(16) float aS[RR][WW];
    __shared__ __align__(16) float tS[WW][RR];
    __shared__ __align__(16) float gS[RR][RR];
    __shared__ __align__(16) float U[WW][RR];
    __shared__ float red[WW];
    __shared__ float w12s[WW];

    const int c = blockIdx.x, i = blockIdx.y;
    const int tid = threadIdx.x;
    const int len = s_l[c];

    for (int idx = tid; idx < RR * WW; idx += 128) {
        int r = idx / WW, w = idx % WW;
        rawS[r][w] = g_attn[(size_t)(i * RR + r) * NN + c * WW + w];
    }
    for (int idx = tid; idx < RR * RR; idx += 128)
        gS[idx / RR][idx % RR] = g_gram[i * RR * RR + idx];
    __syncthreads();

    // per-region: leaky_relu(0.1), word mask, L2-normalize over w
    if (tid < RR) {
        const int r = tid;
        float ss = 0.f;
        #pragma unroll 10
        for (int w = 0; w < WW; w++) {
            float v = rawS[r][w];
            v = (v > 0.f) ? v : 0.1f * v;
            v = (w < len) ? v : 0.f;
            ss += v * v;
            aS[r][w] = v;
        }
        float inv = 1.f / (sqrtf(ss) + 1e-8f);
        #pragma unroll 10
        for (int w = 0; w < WW; w++) aS[r][w] *= inv;
    }
    __syncthreads();

    // per-word: softmax over regions (lambda=9), and w12 = sum t * raw
    if (tid < WW) {
        const int w = tid;
        float mx = -1e30f;
        #pragma unroll
        for (int r = 0; r < RR; r++) mx = fmaxf(mx, aS[r][w]);
        float ssum = 0.f;
        #pragma unroll
        for (int r = 0; r < RR; r++) {
            float e = __expf(9.f * (aS[r][w] - mx));
            tS[w][r] = e;
            ssum += e;
        }
        const float inv = 1.f / ssum;
        float w12 = 0.f;
        #pragma unroll
        for (int r = 0; r < RR; r++) {
            float tv = tS[w][r] * inv;
            tS[w][r] = tv;
            w12 += tv * rawS[r][w];
        }
        w12s[w] = w12;
    }
    __syncthreads();

    // U[w][r0..r0+3] = sum_r2 t[w][r2] * G[r2][r0..r0+3]   (450 float4 items)
    for (int idx = tid; idx < WW * (RR / 4); idx += 128) {
        const int w = idx / (RR / 4);
        const int j = idx % (RR / 4);
        float4 acc = make_float4(0.f, 0.f, 0.f, 0.f);
        #pragma unroll
        for (int r2 = 0; r2 < RR; r2++) {
            const float tv = tS[w][r2];
            const float4 g4 = *(const float4*)&gS[r2][4 * j];
            acc.x += tv * g4.x; acc.y += tv * g4.y;
            acc.z += tv * g4.z; acc.w += tv * g4.w;
        }
        *(float4*)&U[w][4 * j] = acc;
    }
    __syncthreads();

    // per-word: w2^2 = t . U, similarity, masked exp
    if (tid < WW) {
        const int w = tid;
        float w2sq = 0.f;
        #pragma unroll
        for (int r = 0; r < RR; r++) w2sq += U[w][r] * tS[w][r];
        const float w2 = sqrtf(w2sq);
        const float w1v = g_w1[c * WW + w];
        const float denom = fmaxf(w1v * w2, 1e-8f);
        const float sim = w12s[w] / denom;
        red[w] = (w < len) ? expf(6.f * sim) : 0.f;
    }
    __syncthreads();

    if (tid == 0) {
        float sum = 0.f;
        #pragma unroll 10
        for (int w = 0; w < WW; w++) sum += red[w];
        g_scores[i * NI + c] = logf(sum) / 6.f;
    }
}

// ---------------------------------------------------------------------------
// Hinge loss with hardest negatives
// ---------------------------------------------------------------------------
__global__ __launch_bounds__(128) void loss_kernel(float* __restrict__ out) {
    __shared__ float diag[NI];
    __shared__ float partial[NI];
    const int t = threadIdx.x;
    diag[t] = g_scores[t * NI + t];
    __syncthreads();
    const float dt = diag[t];
    float m1 = 0.f, m2 = 0.f;
    for (int c = 0; c < NI; c++) {
        if (c != t) {
            float v = 0.2f + g_scores[t * NI + c] - dt;
            m1 = fmaxf(m1, fmaxf(v, 0.f));
            float u = 0.2f + g_scores[c * NI + t] - dt;
            m2 = fmaxf(m2, fmaxf(u, 0.f));
        }
    }
    partial[t] = m1 + m2;
    __syncthreads();
    if (t == 0) {
        float s = 0.f;
        for (int k = 0; k < NI; k++) s += partial[k];
        out[0] = s;
    }
}

// ---------------------------------------------------------------------------
extern "C" void kernel_launch(void* const* d_in, const int* in_sizes, int n_in,
                              void* d_out, int out_size) {
    const float* im  = (const float*)d_in[0];   // (128, 36, 1024) f32
    const float* s   = (const float*)d_in[1];   // (128, 50, 1024) f32
    const int*   s_l = (const int*)d_in[2];     // (128,) i32
    float* out = (float*)d_out;

    cudaFuncSetAttribute(gemm_mma_bf16, cudaFuncAttributeMaxDynamicSharedMemorySize,
                         GEMM_SMEM);

    convert_split<0><<<MM * DD / (256 * 4), 256>>>(im);
    convert_split<1><<<NN * DD / (256 * 4), 256>>>(s);     // also computes g_w1
    gemm_mma_bf16<<<dim3(NN / 128, MM / 128), 256, GEMM_SMEM>>>();
    gram_partial<<<dim3(GCH, NI), 256>>>(im);
    gram_reduce<<<(NI * RR * RR + 255) / 256, 256>>>();
    pair_kernel<<<dim3(NI, NI), 128>>>(s_l);
    loss_kernel<<<1, 128>>>(out);
}